// round 7
// baseline (speedup 1.0000x reference)
#include <cuda_runtime.h>
#include <cuda_bf16.h>
#include <math.h>
#include <cstdint>

#define NROWS 8192
#define DDIM  64
#define MARGIN 1.1f
#define EPS 1e-8f
#define TILE 128
#define NTILES (NROWS / TILE)     // 64
#define NPREP  NTILES             // 64 prep blocks
#define NGROUPS 544               // sum over bi of ceil((64-bi)/4)
#define ROWB 144                  // padded smem row stride (bytes)
#define BUFB (TILE * ROWB)        // 18432 bytes per tile buffer
// dsm layout: A | B0 | B1 | B2 | csi[128] | csj[512] | red[8]
#define SMEM_TOTAL (4 * BUFB + (128 + 512) * 4 + 32)

// Scratch (no allocs allowed).
__device__ __align__(16) __nv_bfloat16 g_xb[NROWS * DDIM];
__device__ double   g_accum;          // zero-init; last block resets
__device__ unsigned g_prep_done;      // idem
__device__ unsigned g_done_ctr;       // idem

__device__ __forceinline__ uint32_t smem_u32(const void* p) {
    uint32_t a;
    asm("{ .reg .u64 t; cvta.to.shared.u64 t, %1; cvt.u32.u64 %0, t; }"
        : "=r"(a) : "l"(p));
    return a;
}

__device__ __forceinline__ void ldsm_x4(uint32_t& r0, uint32_t& r1,
                                        uint32_t& r2, uint32_t& r3,
                                        uint32_t addr) {
    asm volatile("ldmatrix.sync.aligned.m8n8.x4.shared.b16 {%0,%1,%2,%3}, [%4];"
                 : "=r"(r0), "=r"(r1), "=r"(r2), "=r"(r3) : "r"(addr));
}

__device__ __forceinline__ void mma_16816(float* c, const uint32_t* a,
                                          uint32_t b0, uint32_t b1) {
    asm volatile(
        "mma.sync.aligned.m16n8k16.row.col.f32.bf16.bf16.f32 "
        "{%0,%1,%2,%3}, {%4,%5,%6,%7}, {%8,%9}, {%0,%1,%2,%3};"
        : "+f"(c[0]), "+f"(c[1]), "+f"(c[2]), "+f"(c[3])
        : "r"(a[0]), "r"(a[1]), "r"(a[2]), "r"(a[3]), "r"(b0), "r"(b1));
}

__device__ __forceinline__ void cpa16(uint32_t dst, const void* src) {
    asm volatile("cp.async.cg.shared.global [%0], [%1], 16;"
                 :: "r"(dst), "l"(src) : "memory");
}
#define CPA_COMMIT() asm volatile("cp.async.commit_group;" ::: "memory")
#define CPA_WAIT(n)  asm volatile("cp.async.wait_group %0;" :: "n"(n) : "memory")

// ---------------------------------------------------------------------------
// One fused kernel (3 CTAs/SM). Blocks 0..63 normalize -> bf16 (phase 1).
// All 544 blocks then process a GROUP of up to 4 tiles sharing one A band.
// Each warp computes its 32x64 output as two sequential 32x32 halves to
// keep live registers <= 85 (occupancy 3).
// ---------------------------------------------------------------------------
__global__ __launch_bounds__(256, 3) void fused_kernel(
    const float* __restrict__ x, const int* __restrict__ cls,
    float* __restrict__ out) {

    extern __shared__ __align__(16) char dsm[];
    char*  sA   = dsm;
    char*  sB   = dsm + BUFB;                    // 3 buffers of BUFB
    int*   csi  = (int*)(dsm + 4 * BUFB);
    int*   csj  = csi + 128;                     // 4 x 128
    float* red  = (float*)(csj + 512);

    const int bid  = blockIdx.x;
    const int tid  = threadIdx.x;
    const int wid  = tid >> 5;
    const int lane = tid & 31;

    // ---------------- Phase 1: prep (normalize -> bf16), blocks 0..63 ------
    if (bid < NPREP) {
        int t    = bid * 256 + tid;
        int row  = t >> 1;
        int half = t & 1;
        const float4* xr = (const float4*)(x + (size_t)row * DDIM + half * 32);
        float4 v[8];
        #pragma unroll
        for (int i = 0; i < 8; i++) v[i] = xr[i];
        float s = 0.0f;
        #pragma unroll
        for (int i = 0; i < 8; i++)
            s += v[i].x * v[i].x + v[i].y * v[i].y +
                 v[i].z * v[i].z + v[i].w * v[i].w;
        s += __shfl_xor_sync(0xffffffffu, s, 1);
        float inv = 1.0f / fmaxf(sqrtf(s), EPS);
        __nv_bfloat16* dst = g_xb + (size_t)row * DDIM + half * 32;
        #pragma unroll
        for (int i = 0; i < 8; i++) {
            __nv_bfloat162 p0 = {__float2bfloat16(v[i].x * inv),
                                 __float2bfloat16(v[i].y * inv)};
            __nv_bfloat162 p1 = {__float2bfloat16(v[i].z * inv),
                                 __float2bfloat16(v[i].w * inv)};
            *(__nv_bfloat162*)(dst + i * 4)     = p0;
            *(__nv_bfloat162*)(dst + i * 4 + 2) = p1;
        }
        __syncthreads();
        if (tid == 0) { __threadfence(); atomicAdd(&g_prep_done, 1u); }
    }

    // ---------------- Device-wide wait for prep ----------------------------
    if (tid == 0) {
        unsigned v;
        do {
            asm volatile("ld.acquire.gpu.u32 %0, [%1];"
                         : "=r"(v) : "l"(&g_prep_done));
            if (v < (unsigned)NPREP) __nanosleep(64);
        } while (v < (unsigned)NPREP);
    }
    __syncthreads();

    // ---------------- Group mapping: bid -> (bi, bj0, nb) ------------------
    int rem = bid, bi = 0;
    for (;;) {
        int g = (NTILES - bi + 3) >> 2;
        if (rem < g) break;
        rem -= g; bi++;
    }
    const int bj0 = bi + rem * 4;
    const int nb  = min(4, NTILES - bj0);

    // ---------------- Load A band + classes (once per group) ---------------
    {
        const uint4* Ag = (const uint4*)(g_xb + (size_t)bi * TILE * DDIM);
        #pragma unroll
        for (int r = 0; r < 4; r++) {
            int idx = tid + r * 256;
            int row = idx >> 3;
            int ch  = idx & 7;
            *(uint4*)(sA + row * ROWB + ch * 16) = Ag[idx];
        }
        if (tid < TILE) csi[tid] = cls[bi * TILE + tid];
        for (int q = tid; q < nb * TILE; q += 256)
            csj[q] = cls[bj0 * TILE + q];
    }

    // ---------------- Prefetch B(0) -----------------------------------------
    uint32_t bufu[3] = { smem_u32(sB), smem_u32(sB + BUFB),
                         smem_u32(sB + 2 * BUFB) };
    {
        const char* src = (const char*)(g_xb + (size_t)bj0 * TILE * DDIM);
        #pragma unroll
        for (int r = 0; r < 4; r++) {
            int idx = tid + r * 256;
            int row = idx >> 3;
            int ch  = idx & 7;
            cpa16(bufu[0] + row * ROWB + ch * 16, src + idx * 16);
        }
    }
    CPA_COMMIT();

    const uint32_t a_base = smem_u32(sA);
    const int wm = wid & 3;          // 4 row groups of 32
    const int wn = wid >> 2;         // 2 col groups of 32 (per 64-col half)
    const uint32_t a_lane_off =
        (uint32_t)((wm * 32 + (lane & 15)) * ROWB + ((lane >> 4) << 4));
    // B half h occupies rows (output cols) h*64 + wn*32 .. +32 of the tile.
    const uint32_t b_lane_base =
        (uint32_t)((wn * 32 + (lane & 7) + ((lane >> 4) << 3)) * ROWB +
                   (((lane >> 3) & 1) << 4));
    const float MC = MARGIN - 1.0f;
    const int quad = lane >> 2;
    const int tq   = lane & 3;

    __syncthreads();   // csi visible
    // Row classes for this thread are constant across all tiles: hoist.
    const int ci00 = csi[wm * 32 + quad];          // m=0, low 8 rows
    const int ci01 = csi[wm * 32 + quad + 8];      // m=0, high 8 rows
    const int ci10 = csi[wm * 32 + 16 + quad];     // m=1
    const int ci11 = csi[wm * 32 + 16 + quad + 8];

    float lsum = 0.0f;

    for (int t = 0; t < nb; t++) {
        if (t + 1 < nb) {
            const char* src =
                (const char*)(g_xb + (size_t)(bj0 + t + 1) * TILE * DDIM);
            uint32_t dst = bufu[(t + 1) % 3];
            #pragma unroll
            for (int r = 0; r < 4; r++) {
                int idx = tid + r * 256;
                int row = idx >> 3;
                int ch  = idx & 7;
                cpa16(dst + row * ROWB + ch * 16, src + idx * 16);
            }
            CPA_COMMIT();
            CPA_WAIT(1);
        } else {
            CPA_WAIT(0);
        }
        __syncthreads();

        const uint32_t b_base = bufu[t % 3];
        float tl = 0.0f;

        #pragma unroll
        for (int h = 0; h < 2; h++) {            // two 128x32 halves
            float c[2][4][4];
            #pragma unroll
            for (int m = 0; m < 2; m++)
                #pragma unroll
                for (int n = 0; n < 4; n++)
                    #pragma unroll
                    for (int e = 0; e < 4; e++) c[m][n][e] = 0.0f;

            const uint32_t b_half = b_base + b_lane_base
                                  + (uint32_t)(h * 64 * ROWB);
            #pragma unroll
            for (int k = 0; k < 4; k++) {
                uint32_t a[2][4];
                #pragma unroll
                for (int m = 0; m < 2; m++)
                    ldsm_x4(a[m][0], a[m][1], a[m][2], a[m][3],
                            a_base + a_lane_off + m * 16 * ROWB + k * 32);
                uint32_t b[4][2];
                #pragma unroll
                for (int q = 0; q < 2; q++) {    // 2 x4 = 32 cols
                    uint32_t r0, r1, r2, r3;
                    ldsm_x4(r0, r1, r2, r3,
                            b_half + q * 16 * ROWB + k * 32);
                    b[q * 2 + 0][0] = r0; b[q * 2 + 0][1] = r1;
                    b[q * 2 + 1][0] = r2; b[q * 2 + 1][1] = r3;
                }
                #pragma unroll
                for (int m = 0; m < 2; m++)
                    #pragma unroll
                    for (int n = 0; n < 4; n++)
                        mma_16816(c[m][n], a[m], b[n][0], b[n][1]);
            }

            // ---- Hinge epilogue on this half ----
            const int* cjt = csj + t * TILE + h * 64 + wn * 32;
            float l0 = 0.0f, l1 = 0.0f;
            #pragma unroll
            for (int m = 0; m < 2; m++) {
                const int ci0 = m ? ci10 : ci00;
                const int ci1 = m ? ci11 : ci01;
                #pragma unroll
                for (int n = 0; n < 4; n++) {
                    const int colb = n * 8 + tq * 2;
                    const int cj0  = cjt[colb];
                    const int cj1  = cjt[colb + 1];
                    float v0 = c[m][n][0], v1 = c[m][n][1];
                    float v2 = c[m][n][2], v3 = c[m][n][3];
                    l0 += (ci0 == cj0) ? (1.0f - v0) : fmaxf(v0 + MC, 0.0f);
                    l1 += (ci0 == cj1) ? (1.0f - v1) : fmaxf(v1 + MC, 0.0f);
                    l0 += (ci1 == cj0) ? (1.0f - v2) : fmaxf(v2 + MC, 0.0f);
                    l1 += (ci1 == cj1) ? (1.0f - v3) : fmaxf(v3 + MC, 0.0f);
                }
            }
            tl += l0 + l1;
        }
        lsum += (bj0 + t == bi) ? tl : 2.0f * tl;   // off-diag counted twice
    }

    // ---------------- Group reduce + finalize --------------------------------
    #pragma unroll
    for (int o = 16; o; o >>= 1) lsum += __shfl_xor_sync(0xffffffffu, lsum, o);
    if (lane == 0) red[wid] = lsum;
    __syncthreads();
    if (tid == 0) {
        float tt = 0.0f;
        #pragma unroll
        for (int w = 0; w < 8; w++) tt += red[w];
        atomicAdd(&g_accum, (double)tt);
        __threadfence();
        unsigned old = atomicAdd(&g_done_ctr, 1u);
        if (old == (unsigned)(NGROUPS - 1)) {
            double a = atomicAdd(&g_accum, 0.0);
            out[0] = (float)(a / ((double)NROWS * (double)NROWS));
            g_accum     = 0.0;
            g_done_ctr  = 0u;
            g_prep_done = 0u;
        }
    }
}

extern "C" void kernel_launch(void* const* d_in, const int* in_sizes, int n_in,
                              void* d_out, int out_size) {
    const float* bottleneck = (const float*)d_in[0];
    const int*   class_map  = (const int*)d_in[1];
    float*       out        = (float*)d_out;

    cudaFuncSetAttribute(fused_kernel,
                         cudaFuncAttributeMaxDynamicSharedMemorySize,
                         SMEM_TOTAL);
    fused_kernel<<<NGROUPS, 256, SMEM_TOTAL>>>(bottleneck, class_map, out);
}

// round 8
// speedup vs baseline: 1.1306x; 1.1306x over previous
#include <cuda_runtime.h>
#include <cuda_bf16.h>
#include <math.h>
#include <cstdint>

#define NROWS 8192
#define DDIM  64
#define MARGIN 1.1f
#define EPS 1e-8f
#define TILE 128
#define NTILES (NROWS / TILE)     // 64
#define NPREP  NTILES             // 64 prep blocks
#define NGROUPS 544               // sum over bi of ceil((64-bi)/4)
#define NWORKERS 296              // 2 CTAs/SM x 148 SMs, all wave-1 resident
#define ROWB 144                  // padded smem row stride (bytes)
#define BUFB (TILE * ROWB)        // 18432 bytes per tile buffer
// dsm layout: A | B0 | B1 | B2 | csi[128] | csj[512] | red[8] | unit
#define SMEM_TOTAL (4 * BUFB + (128 + 512) * 4 + 32 + 16)

// Scratch (no allocs allowed).
__device__ __align__(16) __nv_bfloat16 g_xb[NROWS * DDIM];
__device__ double   g_accum;          // zero-init; last block resets
__device__ unsigned g_prep_done;      // idem
__device__ unsigned g_done_ctr;       // idem
__device__ unsigned g_work;           // work-stealing cursor (reset each run)

__device__ __forceinline__ uint32_t smem_u32(const void* p) {
    uint32_t a;
    asm("{ .reg .u64 t; cvta.to.shared.u64 t, %1; cvt.u32.u64 %0, t; }"
        : "=r"(a) : "l"(p));
    return a;
}

__device__ __forceinline__ void ldsm_x4(uint32_t& r0, uint32_t& r1,
                                        uint32_t& r2, uint32_t& r3,
                                        uint32_t addr) {
    asm volatile("ldmatrix.sync.aligned.m8n8.x4.shared.b16 {%0,%1,%2,%3}, [%4];"
                 : "=r"(r0), "=r"(r1), "=r"(r2), "=r"(r3) : "r"(addr));
}

__device__ __forceinline__ void mma_16816(float* c, const uint32_t* a,
                                          uint32_t b0, uint32_t b1) {
    asm volatile(
        "mma.sync.aligned.m16n8k16.row.col.f32.bf16.bf16.f32 "
        "{%0,%1,%2,%3}, {%4,%5,%6,%7}, {%8,%9}, {%0,%1,%2,%3};"
        : "+f"(c[0]), "+f"(c[1]), "+f"(c[2]), "+f"(c[3])
        : "r"(a[0]), "r"(a[1]), "r"(a[2]), "r"(a[3]), "r"(b0), "r"(b1));
}

__device__ __forceinline__ void cpa16(uint32_t dst, const void* src) {
    asm volatile("cp.async.cg.shared.global [%0], [%1], 16;"
                 :: "r"(dst), "l"(src) : "memory");
}
#define CPA_COMMIT() asm volatile("cp.async.commit_group;" ::: "memory")
#define CPA_WAIT(n)  asm volatile("cp.async.wait_group %0;" :: "n"(n) : "memory")

// ---------------------------------------------------------------------------
// Persistent fused kernel (296 resident CTAs). Blocks 0..63 normalize -> bf16
// (phase 1); all blocks then steal GROUPS of up to 4 tiles sharing one A band
// from a global cursor. Loss accumulates in registers across groups; one
// reduce + atomic per block. Last block finalizes mean and resets state.
// ---------------------------------------------------------------------------
__global__ __launch_bounds__(256, 2) void fused_kernel(
    const float* __restrict__ x, const int* __restrict__ cls,
    float* __restrict__ out) {

    extern __shared__ __align__(16) char dsm[];
    char*  sA    = dsm;
    char*  sB    = dsm + BUFB;                    // 3 buffers of BUFB
    int*   csi   = (int*)(dsm + 4 * BUFB);
    int*   csj   = csi + 128;                     // 4 x 128
    float* red   = (float*)(csj + 512);
    int*   sunit = (int*)(red + 8);

    const int bid  = blockIdx.x;
    const int tid  = threadIdx.x;
    const int wid  = tid >> 5;
    const int lane = tid & 31;

    // ---------------- Phase 1: prep (normalize -> bf16), blocks 0..63 ------
    if (bid < NPREP) {
        int t    = bid * 256 + tid;
        int row  = t >> 1;
        int half = t & 1;
        const float4* xr = (const float4*)(x + (size_t)row * DDIM + half * 32);
        float4 v[8];
        #pragma unroll
        for (int i = 0; i < 8; i++) v[i] = xr[i];
        float s = 0.0f;
        #pragma unroll
        for (int i = 0; i < 8; i++)
            s += v[i].x * v[i].x + v[i].y * v[i].y +
                 v[i].z * v[i].z + v[i].w * v[i].w;
        s += __shfl_xor_sync(0xffffffffu, s, 1);
        float inv = 1.0f / fmaxf(sqrtf(s), EPS);
        __nv_bfloat16* dst = g_xb + (size_t)row * DDIM + half * 32;
        #pragma unroll
        for (int i = 0; i < 8; i++) {
            __nv_bfloat162 p0 = {__float2bfloat16(v[i].x * inv),
                                 __float2bfloat16(v[i].y * inv)};
            __nv_bfloat162 p1 = {__float2bfloat16(v[i].z * inv),
                                 __float2bfloat16(v[i].w * inv)};
            *(__nv_bfloat162*)(dst + i * 4)     = p0;
            *(__nv_bfloat162*)(dst + i * 4 + 2) = p1;
        }
        __syncthreads();
        if (tid == 0) { __threadfence(); atomicAdd(&g_prep_done, 1u); }
    }

    // ---------------- Device-wide wait for prep ----------------------------
    if (tid == 0) {
        unsigned v;
        do {
            asm volatile("ld.acquire.gpu.u32 %0, [%1];"
                         : "=r"(v) : "l"(&g_prep_done));
            if (v < (unsigned)NPREP) __nanosleep(64);
        } while (v < (unsigned)NPREP);
    }
    __syncthreads();

    const int wm = wid & 3;
    const int wn = wid >> 2;
    const uint32_t a_base = smem_u32(sA);
    const uint32_t bufu[3] = { smem_u32(sB), smem_u32(sB + BUFB),
                               smem_u32(sB + 2 * BUFB) };
    const uint32_t a_lane_off =
        (uint32_t)((wm * 32 + (lane & 15)) * ROWB + ((lane >> 4) << 4));
    const uint32_t b_lane_off =
        (uint32_t)((wn * 64 + (lane & 7) + ((lane >> 4) << 3)) * ROWB +
                   (((lane >> 3) & 1) << 4));
    const float MC = MARGIN - 1.0f;
    const int quad = lane >> 2;
    const int tq   = lane & 3;

    float lsum = 0.0f;     // carried across ALL stolen groups

    // ==================== Persistent work-stealing loop =====================
    for (;;) {
        if (tid == 0) *sunit = (int)atomicAdd(&g_work, 1u);
        __syncthreads();                 // broadcast unit; smem safe to reuse
        const int unit = *sunit;
        if (unit >= NGROUPS) break;

        // ---- unit -> (bi, bj0, nb) ----
        int rem = unit, bi = 0;
        for (;;) {
            int g = (NTILES - bi + 3) >> 2;
            if (rem < g) break;
            rem -= g; bi++;
        }
        const int bj0 = bi + rem * 4;
        const int nb  = min(4, NTILES - bj0);

        // ---- Load A band + classes (once per group) ----
        {
            const uint4* Ag = (const uint4*)(g_xb + (size_t)bi * TILE * DDIM);
            #pragma unroll
            for (int r = 0; r < 4; r++) {
                int idx = tid + r * 256;
                int row = idx >> 3;
                int ch  = idx & 7;
                *(uint4*)(sA + row * ROWB + ch * 16) = Ag[idx];
            }
            if (tid < TILE) csi[tid] = __ldg(&cls[bi * TILE + tid]);
            for (int q = tid; q < nb * TILE; q += 256)
                csj[q] = __ldg(&cls[bj0 * TILE + q]);
        }

        // ---- Prefetch B(0) ----
        {
            const char* src = (const char*)(g_xb + (size_t)bj0 * TILE * DDIM);
            #pragma unroll
            for (int r = 0; r < 4; r++) {
                int idx = tid + r * 256;
                int row = idx >> 3;
                int ch  = idx & 7;
                cpa16(bufu[0] + row * ROWB + ch * 16, src + idx * 16);
            }
        }
        CPA_COMMIT();
        __syncthreads();                 // csi/csj visible

        // Row classes constant for the whole group: hoist.
        const int ci00 = csi[wm * 32 + quad];
        const int ci01 = csi[wm * 32 + quad + 8];
        const int ci10 = csi[wm * 32 + 16 + quad];
        const int ci11 = csi[wm * 32 + 16 + quad + 8];

        for (int t = 0; t < nb; t++) {
            if (t + 1 < nb) {
                const char* src =
                    (const char*)(g_xb + (size_t)(bj0 + t + 1) * TILE * DDIM);
                uint32_t dst = bufu[(t + 1) % 3];
                #pragma unroll
                for (int r = 0; r < 4; r++) {
                    int idx = tid + r * 256;
                    int row = idx >> 3;
                    int ch  = idx & 7;
                    cpa16(dst + row * ROWB + ch * 16, src + idx * 16);
                }
                CPA_COMMIT();
                CPA_WAIT(1);
            } else {
                CPA_WAIT(0);
            }
            __syncthreads();

            const uint32_t b_base = bufu[t % 3];

            float c[2][8][4];
            #pragma unroll
            for (int m = 0; m < 2; m++)
                #pragma unroll
                for (int n = 0; n < 8; n++)
                    #pragma unroll
                    for (int e = 0; e < 4; e++) c[m][n][e] = 0.0f;

            #pragma unroll
            for (int k = 0; k < 4; k++) {
                uint32_t a[2][4];
                #pragma unroll
                for (int m = 0; m < 2; m++)
                    ldsm_x4(a[m][0], a[m][1], a[m][2], a[m][3],
                            a_base + a_lane_off + m * 16 * ROWB + k * 32);
                uint32_t b[8][2];
                #pragma unroll
                for (int q = 0; q < 4; q++) {
                    uint32_t r0, r1, r2, r3;
                    ldsm_x4(r0, r1, r2, r3,
                            b_base + b_lane_off + q * 16 * ROWB + k * 32);
                    b[q * 2 + 0][0] = r0; b[q * 2 + 0][1] = r1;
                    b[q * 2 + 1][0] = r2; b[q * 2 + 1][1] = r3;
                }
                #pragma unroll
                for (int m = 0; m < 2; m++)
                    #pragma unroll
                    for (int n = 0; n < 8; n++)
                        mma_16816(c[m][n], a[m], b[n][0], b[n][1]);
            }

            // ---- Hinge epilogue on fragments ----
            const int* cjt = csj + t * TILE;
            float l0 = 0.0f, l1 = 0.0f;
            #pragma unroll
            for (int m = 0; m < 2; m++) {
                const int ci0 = m ? ci10 : ci00;
                const int ci1 = m ? ci11 : ci01;
                #pragma unroll
                for (int n = 0; n < 8; n++) {
                    const int colb = wn * 64 + n * 8 + tq * 2;
                    const int cj0  = cjt[colb];
                    const int cj1  = cjt[colb + 1];
                    float v0 = c[m][n][0], v1 = c[m][n][1];
                    float v2 = c[m][n][2], v3 = c[m][n][3];
                    l0 += (ci0 == cj0) ? (1.0f - v0) : fmaxf(v0 + MC, 0.0f);
                    l1 += (ci0 == cj1) ? (1.0f - v1) : fmaxf(v1 + MC, 0.0f);
                    l0 += (ci1 == cj0) ? (1.0f - v2) : fmaxf(v2 + MC, 0.0f);
                    l1 += (ci1 == cj1) ? (1.0f - v3) : fmaxf(v3 + MC, 0.0f);
                }
            }
            float tl = l0 + l1;
            lsum += (bj0 + t == bi) ? tl : 2.0f * tl;
        }
        __syncthreads();   // all warps done with csi/csj/sA before next unit
    }

    // ---------------- One reduce + atomic per block --------------------------
    #pragma unroll
    for (int o = 16; o; o >>= 1) lsum += __shfl_xor_sync(0xffffffffu, lsum, o);
    if (lane == 0) red[wid] = lsum;
    __syncthreads();
    if (tid == 0) {
        float tt = 0.0f;
        #pragma unroll
        for (int w = 0; w < 8; w++) tt += red[w];
        atomicAdd(&g_accum, (double)tt);
        __threadfence();
        unsigned old = atomicAdd(&g_done_ctr, 1u);
        if (old == (unsigned)(NWORKERS - 1)) {
            double a = atomicAdd(&g_accum, 0.0);
            out[0] = (float)(a / ((double)NROWS * (double)NROWS));
            g_accum     = 0.0;
            g_done_ctr  = 0u;
            g_prep_done = 0u;
            g_work      = 0u;
        }
    }
}

extern "C" void kernel_launch(void* const* d_in, const int* in_sizes, int n_in,
                              void* d_out, int out_size) {
    const float* bottleneck = (const float*)d_in[0];
    const int*   class_map  = (const int*)d_in[1];
    float*       out        = (float*)d_out;

    cudaFuncSetAttribute(fused_kernel,
                         cudaFuncAttributeMaxDynamicSharedMemorySize,
                         SMEM_TOTAL);
    fused_kernel<<<NWORKERS, 256, SMEM_TOTAL>>>(bottleneck, class_map, out);
}